// round 1
// baseline (speedup 1.0000x reference)
#include <cuda_runtime.h>
#include <cstdint>

#define BATCH 32
#define NPTS  65536
#define SSAMP 512
#define CPB   4                 // CTAs per batch
#define PSH   (NPTS / CPB)      // 16384 points per CTA shard
#define TPB   1024
#define PPT   (PSH / TPB)       // 16 points per thread

struct Cand { unsigned long long key; float x, y, z; };

__device__ Cand      g_cand[2][BATCH][CPB];
__device__ unsigned  g_arrive[BATCH];
__device__ int       g_idx[BATCH][SSAMP];

// Reset per-launch counters (separate graph node; stream-ordered before FPS).
__global__ void init_kernel() {
    int t = threadIdx.x;
    if (t < BATCH) g_arrive[t] = 0;
}

// 128 CTAs: 4 per batch, each holds its 16384-point shard (SoA) in SMEM for
// all iterations. dist[] lives in registers. Per-batch 4-CTA sync via an L2
// monotonic counter with release/acquire + parity double-buffered candidates.
__global__ void __launch_bounds__(TPB, 1) fps_kernel(const float* __restrict__ xyz) {
    extern __shared__ float sm[];
    const int cta  = blockIdx.x;
    const int b    = cta >> 2;
    const int c    = cta & 3;
    const int base = c * PSH;
    const int t    = threadIdx.x;
    const float* X = xyz + (size_t)b * NPTS * 3;

    float* xs = sm;
    float* ys = sm + PSH;
    float* zs = sm + 2 * PSH;
    unsigned long long* red = (unsigned long long*)(sm + 3 * PSH);
    float* bc = (float*)(red + 32);   // broadcast: centroid x,y,z

    // Load shard, deinterleave [P,3] -> SoA (coalesced global reads; one-time).
    for (int i = t; i < 3 * PSH; i += TPB) {
        float v = X[(size_t)base * 3 + i];
        int p = i / 3;
        int k = i - 3 * p;
        sm[k * PSH + p] = v;
    }

    float dist[PPT];
#pragma unroll
    for (int j = 0; j < PPT; j++) dist[j] = 1e10f;

    // Initial centroid = point 0 of the batch (uniform LDG broadcast).
    float cx = X[0], cy = X[1], cz = X[2];
    if (c == 0 && t == 0) g_idx[b][0] = 0;

    __syncthreads();

    for (int iter = 0; iter < SSAMP - 1; iter++) {
        // --- scan: update dist, track per-thread argmax ---
        float bv = -1.0f;
        int   bp = 0;
#pragma unroll
        for (int j = 0; j < PPT; j++) {
            int p = t + j * TPB;                 // conflict-free LDS
            float dx = xs[p] - cx;
            float dy = ys[p] - cy;
            float dz = zs[p] - cz;
            float d  = fmaf(dz, dz, fmaf(dy, dy, dx * dx));
            float v  = fminf(dist[j], d);
            dist[j] = v;
            if (v > bv) { bv = v; bp = p; }      // strict > keeps smallest j on tie
        }
        // key: max dist wins; exact tie -> smallest global index (matches jnp.argmax)
        unsigned long long key =
            ((unsigned long long)__float_as_uint(bv) << 32) |
            (unsigned)(~(unsigned)(base + bp));

#pragma unroll
        for (int o = 16; o; o >>= 1) {
            unsigned long long other = __shfl_xor_sync(0xffffffffu, key, o);
            if (other > key) key = other;
        }
        if ((t & 31) == 0) red[t >> 5] = key;
        __syncthreads();                          // sync A

        if (t < 32) {
            unsigned long long k2 = red[t];
#pragma unroll
            for (int o = 16; o; o >>= 1) {
                unsigned long long other = __shfl_xor_sync(0xffffffffu, k2, o);
                if (other > k2) k2 = other;
            }
            if (t == 0) {
                int widx = (int)(~(unsigned)k2);  // this CTA's best global index
                int off  = widx - base;
                Cand cd;
                cd.key = k2;
                cd.x = xs[off]; cd.y = ys[off]; cd.z = zs[off];
                int par = iter & 1;
                g_cand[par][b][c] = cd;
                __threadfence();                  // release
                atomicAdd(&g_arrive[b], 1u);
                unsigned target = 4u * (unsigned)(iter + 1);
                unsigned v;
                for (;;) {
                    asm volatile("ld.acquire.gpu.u32 %0, [%1];"
                                 : "=r"(v) : "l"(&g_arrive[b]) : "memory");
                    if (v >= target) break;
                    __nanosleep(64);
                }
                __threadfence();                  // acquire side belt+braces
                Cand best = g_cand[par][b][0];
#pragma unroll
                for (int q = 1; q < CPB; q++) {
                    Cand o = g_cand[par][b][q];
                    if (o.key > best.key) best = o;
                }
                bc[0] = best.x; bc[1] = best.y; bc[2] = best.z;
                if (c == 0) g_idx[b][iter + 1] = (int)(~(unsigned)best.key);
            }
        }
        __syncthreads();                          // sync B
        cx = bc[0]; cy = bc[1]; cz = bc[2];
        // (bc is only rewritten after the NEXT sync A -> no extra barrier needed)
    }
}

// Gather: out = [B,S,3] xyz_sampled then [B,S,64] f_sampled (contiguous).
__global__ void gather_kernel(const float* __restrict__ xyz,
                              const float* __restrict__ f,
                              float* __restrict__ out) {
    int sb = blockIdx.x;                 // 0 .. B*S-1
    int b  = sb >> 9;
    int j  = sb & (SSAMP - 1);
    int idx = g_idx[b][j];
    int t  = threadIdx.x;                // 64 threads
    const float* fr = f + ((size_t)b * NPTS + idx) * 64;
    float* fo = out + (size_t)BATCH * SSAMP * 3 + ((size_t)b * SSAMP + j) * 64;
    fo[t] = fr[t];
    if (t < 3) {
        out[((size_t)b * SSAMP + j) * 3 + t] =
            xyz[((size_t)b * NPTS + idx) * 3 + t];
    }
}

extern "C" void kernel_launch(void* const* d_in, const int* in_sizes, int n_in,
                              void* d_out, int out_size) {
    const float* xyz = (const float*)d_in[0];
    const float* f   = (const float*)d_in[1];
    float* out = (float*)d_out;

    size_t smem = 3u * PSH * sizeof(float) + 32 * sizeof(unsigned long long) + 16;
    cudaFuncSetAttribute(fps_kernel,
                         cudaFuncAttributeMaxDynamicSharedMemorySize, (int)smem);

    init_kernel<<<1, 32>>>();
    fps_kernel<<<BATCH * CPB, TPB, smem>>>(xyz);
    gather_kernel<<<BATCH * SSAMP, 64>>>(xyz, f, out);
}

// round 2
// speedup vs baseline: 1.6987x; 1.6987x over previous
#include <cuda_runtime.h>
#include <cstdint>

#define BATCH 32
#define NPTS  65536
#define SSAMP 512
#define CPB   4                 // CTAs per batch = cluster size
#define PSH   (NPTS / CPB)      // 16384 points per CTA shard
#define TPB   1024
#define PAIRS (PSH / (2 * TPB)) // 8 point-pairs per thread
#define PPT   (2 * PAIRS)       // 16 points per thread

__device__ int g_idx[BATCH][SSAMP];

// ---- packed f32x2 helpers (IEEE-identical to scalar ops) ----
#define ADD_F32X2(out, a, b) \
    asm("add.rn.f32x2 %0, %1, %2;" : "=l"(out) : "l"(a), "l"(b))
#define MUL_F32X2(out, a, b) \
    asm("mul.rn.f32x2 %0, %1, %2;" : "=l"(out) : "l"(a), "l"(b))
#define FMA_F32X2(out, a, b, c) \
    asm("fma.rn.f32x2 %0, %1, %2, %3;" : "=l"(out) : "l"(a), "l"(b), "l"(c))
#define PACK_F32X2(out, lo, hi) \
    asm("mov.b64 %0, {%1, %2};" : "=l"(out) : "r"(lo), "r"(hi))
#define UNPACK_F32X2(lo, hi, in) \
    asm("mov.b64 {%0, %1}, %2;" : "=r"(lo), "=r"(hi) : "l"(in))

// One cluster of 4 CTAs per batch. Each CTA holds a 16384-point SoA shard in
// SMEM for all 511 iterations; dist[] lives in registers. The per-iteration
// 4-CTA candidate exchange goes through DSMEM (st.shared::cluster) ordered by
// one cluster barrier (arrive=release / wait=acquire) — no global memory, no
// atomics, no spin. Parity double-buffered slots make one barrier sufficient.
__global__ void __launch_bounds__(TPB, 1) __cluster_dims__(CPB, 1, 1)
fps_kernel(const float* __restrict__ xyz) {
    extern __shared__ float sm[];
    const int cta  = blockIdx.x;
    const int b    = cta >> 2;          // batch
    const int c    = cta & 3;           // rank in cluster
    const int base = c * PSH;
    const int t    = threadIdx.x;
    const float* X = xyz + (size_t)b * NPTS * 3;

    float* xs = sm;
    float* ys = sm + PSH;
    float* zs = sm + 2 * PSH;
    unsigned long long* red = (unsigned long long*)(sm + 3 * PSH); // 32 keys
    char* ex = (char*)(red + 32);       // 2 parity x 4 rank x 32B slots

    // Load shard, deinterleave [P,3] -> SoA (coalesced, one-time).
    for (int i = t; i < 3 * PSH; i += TPB) {
        float v = X[(size_t)base * 3 + i];
        int p = i / 3;
        int k = i - 3 * p;
        sm[k * PSH + p] = v;
    }

    float dist[PPT];
#pragma unroll
    for (int j = 0; j < PPT; j++) dist[j] = 1e10f;

    float cx = X[0], cy = X[1], cz = X[2];   // first centroid = point 0
    if (c == 0 && t == 0) g_idx[b][0] = 0;

    __syncthreads();

    const unsigned long long* xs2 = (const unsigned long long*)xs;
    const unsigned long long* ys2 = (const unsigned long long*)ys;
    const unsigned long long* zs2 = (const unsigned long long*)zs;
    uint32_t ex_base = (uint32_t)__cvta_generic_to_shared(ex);

    for (int iter = 0; iter < SSAMP - 1; iter++) {
        const int par = iter & 1;
        // packed (-c, -c): x + (-c) is IEEE-identical to x - c
        unsigned long long ncx2, ncy2, ncz2;
        {
            uint32_t nx = __float_as_uint(-cx);
            uint32_t ny = __float_as_uint(-cy);
            uint32_t nz = __float_as_uint(-cz);
            PACK_F32X2(ncx2, nx, nx);
            PACK_F32X2(ncy2, ny, ny);
            PACK_F32X2(ncz2, nz, nz);
        }

        // --- scan: packed distance update + running max ---
        float bv = -1.0f;
#pragma unroll
        for (int jj = 0; jj < PAIRS; jj++) {
            int q = t + jj * TPB;                 // pair index; points 2q,2q+1
            unsigned long long x2 = xs2[q];
            unsigned long long y2 = ys2[q];
            unsigned long long z2 = zs2[q];
            unsigned long long dx2, dy2, dz2, s2;
            ADD_F32X2(dx2, x2, ncx2);
            ADD_F32X2(dy2, y2, ncy2);
            ADD_F32X2(dz2, z2, ncz2);
            MUL_F32X2(s2, dx2, dx2);              // dx*dx
            FMA_F32X2(s2, dy2, dy2, s2);          // fmaf(dy,dy,·)
            FMA_F32X2(s2, dz2, dz2, s2);          // fmaf(dz,dz,·)
            uint32_t lo, hi;
            UNPACK_F32X2(lo, hi, s2);
            float v0 = fminf(dist[2 * jj],     __uint_as_float(lo));
            float v1 = fminf(dist[2 * jj + 1], __uint_as_float(hi));
            dist[2 * jj]     = v0;
            dist[2 * jj + 1] = v1;
            bv = fmaxf(bv, fmaxf(v0, v1));
        }
        // locate smallest global index attaining bv (descending k -> first hit)
        int bp = 0;
#pragma unroll
        for (int k = PPT - 1; k >= 0; k--) {
            int jj = k >> 1;
            int p  = 2 * (t + jj * TPB) + (k & 1);
            if (dist[k] == bv) bp = p;
        }
        // key: max dist wins; exact tie -> smallest global index
        unsigned long long key =
            ((unsigned long long)__float_as_uint(bv) << 32) |
            (unsigned)(~(unsigned)(base + bp));

#pragma unroll
        for (int o = 16; o; o >>= 1) {
            unsigned long long other = __shfl_xor_sync(0xffffffffu, key, o);
            if (other > key) key = other;
        }
        if ((t & 31) == 0) red[t >> 5] = key;
        __syncthreads();

        // warp 0: CTA-level reduce + DSMEM broadcast to all 4 cluster ranks
        if (t < 32) {
            unsigned long long k2 = red[t];
#pragma unroll
            for (int o = 16; o; o >>= 1) {
                unsigned long long other = __shfl_xor_sync(0xffffffffu, k2, o);
                if (other > k2) k2 = other;
            }
            int widx = (int)(~(unsigned)k2);
            int off  = widx - base;
            float wx = xs[off], wy = ys[off], wz = zs[off];  // broadcast LDS
            if (t < CPB) {
                uint32_t lslot = ex_base + (uint32_t)(par * CPB + c) * 32u;
                uint32_t raddr;
                asm("mapa.shared::cluster.u32 %0, %1, %2;"
                    : "=r"(raddr) : "r"(lslot), "r"(t));
                unsigned long long xy;
                PACK_F32X2(xy, __float_as_uint(wx), __float_as_uint(wy));
                asm volatile("st.shared::cluster.u64 [%0], %1;"
                             :: "r"(raddr), "l"(k2) : "memory");
                asm volatile("st.shared::cluster.u64 [%0+8], %1;"
                             :: "r"(raddr), "l"(xy) : "memory");
                asm volatile("st.shared::cluster.u32 [%0+16], %1;"
                             :: "r"(raddr), "r"(__float_as_uint(wz)) : "memory");
            }
        }
        // arrive = release (orders the DSMEM stores), wait = acquire
        asm volatile("barrier.cluster.arrive.aligned;" ::: "memory");
        asm volatile("barrier.cluster.wait.aligned;" ::: "memory");

        // every thread reduces the 4 candidates locally (broadcast LDS, no sync)
        {
            const unsigned long long* slots =
                (const unsigned long long*)(ex + par * CPB * 32);
            unsigned long long kb = slots[0];
            int rb = 0;
            unsigned long long k1 = slots[4], k2s = slots[8], k3 = slots[12];
            if (k1  > kb) { kb = k1;  rb = 1; }
            if (k2s > kb) { kb = k2s; rb = 2; }
            if (k3  > kb) { kb = k3;  rb = 3; }
            const float* sp = (const float*)(ex + (par * CPB + rb) * 32 + 8);
            cx = sp[0]; cy = sp[1]; cz = sp[2];
            if (c == 0 && t == 0)
                g_idx[b][iter + 1] = (int)(~(unsigned)kb);
        }
    }
}

// Gather: out = [B,S,3] xyz_sampled then [B,S,64] f_sampled (contiguous).
__global__ void gather_kernel(const float* __restrict__ xyz,
                              const float* __restrict__ f,
                              float* __restrict__ out) {
    int sb = blockIdx.x;                 // 0 .. B*S-1
    int b  = sb >> 9;
    int j  = sb & (SSAMP - 1);
    int idx = g_idx[b][j];
    int t  = threadIdx.x;                // 64 threads
    const float* fr = f + ((size_t)b * NPTS + idx) * 64;
    float* fo = out + (size_t)BATCH * SSAMP * 3 + ((size_t)b * SSAMP + j) * 64;
    fo[t] = fr[t];
    if (t < 3) {
        out[((size_t)b * SSAMP + j) * 3 + t] =
            xyz[((size_t)b * NPTS + idx) * 3 + t];
    }
}

extern "C" void kernel_launch(void* const* d_in, const int* in_sizes, int n_in,
                              void* d_out, int out_size) {
    const float* xyz = (const float*)d_in[0];
    const float* f   = (const float*)d_in[1];
    float* out = (float*)d_out;

    size_t smem = 3u * PSH * sizeof(float)
                + 32 * sizeof(unsigned long long)
                + 2 * CPB * 32;
    cudaFuncSetAttribute(fps_kernel,
                         cudaFuncAttributeMaxDynamicSharedMemorySize, (int)smem);

    fps_kernel<<<BATCH * CPB, TPB, smem>>>(xyz);
    gather_kernel<<<BATCH * SSAMP, 64>>>(xyz, f, out);
}

// round 3
// speedup vs baseline: 1.8400x; 1.0832x over previous
#include <cuda_runtime.h>
#include <cstdint>

#define BATCH 32
#define NPTS  65536
#define SSAMP 512
#define CPB   4                 // CTAs per batch = cluster size
#define PSH   (NPTS / CPB)      // 16384 points per CTA shard
#define TPB   512
#define PAIRS (PSH / (2 * TPB)) // 16 point-pairs per thread
#define SPAIR 8                 // pairs kept in SMEM
#define RPAIR (PAIRS - SPAIR)   // pairs kept in registers
#define PPT   (2 * PAIRS)       // 32 points per thread

__device__ int g_idx[BATCH][SSAMP];

// ---- packed f32x2 helpers (IEEE-identical to scalar ops) ----
#define ADD_F32X2(out, a, b) \
    asm("add.rn.f32x2 %0, %1, %2;" : "=l"(out) : "l"(a), "l"(b))
#define MUL_F32X2(out, a, b) \
    asm("mul.rn.f32x2 %0, %1, %2;" : "=l"(out) : "l"(a), "l"(b))
#define FMA_F32X2(out, a, b, c) \
    asm("fma.rn.f32x2 %0, %1, %2, %3;" : "=l"(out) : "l"(a), "l"(b), "l"(c))
#define PACK_F32X2(out, lo, hi) \
    asm("mov.b64 %0, {%1, %2};" : "=l"(out) : "r"(lo), "r"(hi))
#define UNPACK_F32X2(lo, hi, in) \
    asm("mov.b64 {%0, %1}, %2;" : "=r"(lo), "=r"(hi) : "l"(in))

// Cluster of 4 CTAs per batch. Shard: 16384 pts SoA; half the per-thread
// points live in registers (halving SMEM crossbar traffic), dist[] in regs.
// Per-iteration exchange: warp0 lanes 0-3 push the CTA candidate to all 4
// ranks via st.shared::cluster + remote mbarrier.arrive.release.cluster;
// everyone waits on the LOCAL parity mbarrier (try_wait ~90 cyc) instead of
// a full cluster barrier (~490 cyc).
__global__ void __launch_bounds__(TPB, 1) __cluster_dims__(CPB, 1, 1)
fps_kernel(const float* __restrict__ xyz) {
    extern __shared__ float sm[];
    const int cta  = blockIdx.x;
    const int b    = cta >> 2;          // batch
    const int c    = cta & 3;           // rank in cluster
    const int base = c * PSH;
    const int t    = threadIdx.x;
    const float* X = xyz + (size_t)b * NPTS * 3;

    float* xs = sm;
    float* ys = sm + PSH;
    float* zs = sm + 2 * PSH;
    unsigned long long* red = (unsigned long long*)(sm + 3 * PSH); // 16 keys
    char* ex = (char*)(red + 16);       // 2 parity x 4 rank x 32B slots
    unsigned long long* mbar = (unsigned long long*)(ex + 2 * CPB * 32); // 2 mbarriers

    // Load shard, deinterleave [P,3] -> SoA (coalesced, one-time).
    for (int i = t; i < 3 * PSH; i += TPB) {
        float v = X[(size_t)base * 3 + i];
        int p = i / 3;
        int k = i - 3 * p;
        sm[k * PSH + p] = v;
    }

    uint32_t mbar_base = (uint32_t)__cvta_generic_to_shared(mbar);
    if (t == 0) {
        asm volatile("mbarrier.init.shared.b64 [%0], %1;"
                     :: "r"(mbar_base), "r"((unsigned)CPB) : "memory");
        asm volatile("mbarrier.init.shared.b64 [%0], %1;"
                     :: "r"(mbar_base + 8), "r"((unsigned)CPB) : "memory");
    }
    __syncthreads();
    // peers' mbarriers must be initialized before any remote arrive
    asm volatile("barrier.cluster.arrive.aligned;" ::: "memory");
    asm volatile("barrier.cluster.wait.aligned;" ::: "memory");

    const unsigned long long* xs2 = (const unsigned long long*)xs;
    const unsigned long long* ys2 = (const unsigned long long*)ys;
    const unsigned long long* zs2 = (const unsigned long long*)zs;

    // register-resident half: pairs [SPAIR, PAIRS)
    unsigned long long rx[RPAIR], ry[RPAIR], rz[RPAIR];
#pragma unroll
    for (int j = 0; j < RPAIR; j++) {
        int q = t + (SPAIR + j) * TPB;
        rx[j] = xs2[q]; ry[j] = ys2[q]; rz[j] = zs2[q];
    }

    float dist[PPT];
#pragma unroll
    for (int j = 0; j < PPT; j++) dist[j] = 1e10f;

    float cx = X[0], cy = X[1], cz = X[2];   // first centroid = point 0
    if (c == 0 && t == 0) g_idx[b][0] = 0;

    uint32_t ex_base = (uint32_t)__cvta_generic_to_shared(ex);

    for (int iter = 0; iter < SSAMP - 1; iter++) {
        const int par = iter & 1;
        const unsigned ph = (unsigned)((iter >> 1) & 1);
        // packed (-c,-c): x + (-c) is IEEE-identical to x - c
        unsigned long long ncx2, ncy2, ncz2;
        {
            uint32_t nx = __float_as_uint(-cx);
            uint32_t ny = __float_as_uint(-cy);
            uint32_t nz = __float_as_uint(-cz);
            PACK_F32X2(ncx2, nx, nx);
            PACK_F32X2(ncy2, ny, ny);
            PACK_F32X2(ncz2, nz, nz);
        }

        // --- scan: packed distance update + running max ---
        float bv = -1.0f;
#pragma unroll
        for (int jj = 0; jj < PAIRS; jj++) {
            int q = t + jj * TPB;
            unsigned long long x2, y2, z2;
            if (jj < SPAIR) { x2 = xs2[q]; y2 = ys2[q]; z2 = zs2[q]; }
            else { x2 = rx[jj - SPAIR]; y2 = ry[jj - SPAIR]; z2 = rz[jj - SPAIR]; }
            unsigned long long dx2, dy2, dz2, s2;
            ADD_F32X2(dx2, x2, ncx2);
            ADD_F32X2(dy2, y2, ncy2);
            ADD_F32X2(dz2, z2, ncz2);
            MUL_F32X2(s2, dx2, dx2);
            FMA_F32X2(s2, dy2, dy2, s2);
            FMA_F32X2(s2, dz2, dz2, s2);
            uint32_t lo, hi;
            UNPACK_F32X2(lo, hi, s2);
            float v0 = fminf(dist[2 * jj],     __uint_as_float(lo));
            float v1 = fminf(dist[2 * jj + 1], __uint_as_float(hi));
            dist[2 * jj]     = v0;
            dist[2 * jj + 1] = v1;
            bv = fmaxf(bv, fmaxf(v0, v1));
        }
        // locate smallest global index attaining bv (descending k -> first hit)
        int bp = 0;
#pragma unroll
        for (int k = PPT - 1; k >= 0; k--) {
            int p = 2 * (t + (k >> 1) * TPB) + (k & 1);
            if (dist[k] == bv) bp = p;
        }
        unsigned long long key =
            ((unsigned long long)__float_as_uint(bv) << 32) |
            (unsigned)(~(unsigned)(base + bp));

#pragma unroll
        for (int o = 16; o; o >>= 1) {
            unsigned long long other = __shfl_xor_sync(0xffffffffu, key, o);
            if (other > key) key = other;
        }
        if ((t & 31) == 0) red[t >> 5] = key;
        __syncthreads();

        // warp 0: reduce 16 warp keys, push candidate to all 4 ranks
        if (t < 32) {
            unsigned long long k2 = red[t & 15];
#pragma unroll
            for (int o = 8; o; o >>= 1) {
                unsigned long long other = __shfl_xor_sync(0xffffffffu, k2, o);
                if (other > k2) k2 = other;
            }
            int widx = (int)(~(unsigned)k2);
            int off  = widx - base;
            float wx = xs[off], wy = ys[off], wz = zs[off];  // broadcast LDS
            if (t < CPB) {
                // send this CTA's candidate to rank t's slot[c], then arrive
                uint32_t lslot = ex_base + (uint32_t)(par * CPB + c) * 32u;
                uint32_t raddr, rmbar;
                asm("mapa.shared::cluster.u32 %0, %1, %2;"
                    : "=r"(raddr) : "r"(lslot), "r"(t));
                asm("mapa.shared::cluster.u32 %0, %1, %2;"
                    : "=r"(rmbar) : "r"(mbar_base + (uint32_t)par * 8u), "r"(t));
                unsigned long long xy;
                PACK_F32X2(xy, __float_as_uint(wx), __float_as_uint(wy));
                asm volatile("st.shared::cluster.u64 [%0], %1;"
                             :: "r"(raddr), "l"(k2) : "memory");
                asm volatile("st.shared::cluster.u64 [%0+8], %1;"
                             :: "r"(raddr), "l"(xy) : "memory");
                asm volatile("st.shared::cluster.u32 [%0+16], %1;"
                             :: "r"(raddr), "r"(__float_as_uint(wz)) : "memory");
                asm volatile(
                    "mbarrier.arrive.release.cluster.shared::cluster.b64 _, [%0];"
                    :: "r"(rmbar) : "memory");
            }
        }

        // everyone waits on the LOCAL parity mbarrier (acquire, cluster scope)
        {
            uint32_t mb = mbar_base + (uint32_t)par * 8u;
            uint32_t done;
            do {
                asm volatile(
                    "{\n\t.reg .pred p;\n\t"
                    "mbarrier.try_wait.parity.acquire.cluster.shared::cta.b64 p, [%1], %2;\n\t"
                    "selp.b32 %0, 1, 0, p;\n\t}"
                    : "=r"(done) : "r"(mb), "r"(ph) : "memory");
            } while (!done);
        }

        // every thread reduces the 4 candidates locally (broadcast LDS)
        {
            const unsigned long long* slots =
                (const unsigned long long*)(ex + par * CPB * 32);
            unsigned long long kb = slots[0];
            int rb = 0;
            unsigned long long k1 = slots[4], k2s = slots[8], k3 = slots[12];
            if (k1  > kb) { kb = k1;  rb = 1; }
            if (k2s > kb) { kb = k2s; rb = 2; }
            if (k3  > kb) { kb = k3;  rb = 3; }
            const float* sp = (const float*)(ex + (par * CPB + rb) * 32 + 8);
            cx = sp[0]; cy = sp[1]; cz = sp[2];
            if (c == 0 && t == 0)
                g_idx[b][iter + 1] = (int)(~(unsigned)kb);
        }
    }
}

// Gather: out = [B,S,3] xyz_sampled then [B,S,64] f_sampled. float4 copies.
__global__ void gather_kernel(const float* __restrict__ xyz,
                              const float* __restrict__ f,
                              float* __restrict__ out) {
    int r    = blockIdx.x * 4 + (threadIdx.x >> 4);  // row 0 .. B*S-1
    int lane = threadIdx.x & 15;
    int b = r >> 9;
    int j = r & (SSAMP - 1);
    int idx = g_idx[b][j];
    const float4* fr = (const float4*)(f + ((size_t)b * NPTS + idx) * 64);
    float4* fo = (float4*)(out + (size_t)BATCH * SSAMP * 3 +
                           ((size_t)b * SSAMP + j) * 64);
    fo[lane] = fr[lane];
    if (lane < 3) {
        out[((size_t)b * SSAMP + j) * 3 + lane] =
            xyz[((size_t)b * NPTS + idx) * 3 + lane];
    }
}

extern "C" void kernel_launch(void* const* d_in, const int* in_sizes, int n_in,
                              void* d_out, int out_size) {
    const float* xyz = (const float*)d_in[0];
    const float* f   = (const float*)d_in[1];
    float* out = (float*)d_out;

    size_t smem = 3u * PSH * sizeof(float)
                + 16 * sizeof(unsigned long long)   // red
                + 2 * CPB * 32                      // exchange slots
                + 2 * sizeof(unsigned long long);   // mbarriers
    cudaFuncSetAttribute(fps_kernel,
                         cudaFuncAttributeMaxDynamicSharedMemorySize, (int)smem);

    fps_kernel<<<BATCH * CPB, TPB, smem>>>(xyz);
    gather_kernel<<<(BATCH * SSAMP) / 4, 64>>>(xyz, f, out);
}